// round 5
// baseline (speedup 1.0000x reference)
#include <cuda_runtime.h>
#include <cstdint>
#include <cstddef>

#define N_TOK 4096
#define HDIM  1024
#define NE    8
#define CAP   1536

// ---------------- scratch (static device globals: no allocation) ----------------
// X and Wt stored tf32-split AND k-permuted within each 8-group: order [0,4,1,5,2,6,3,7]
__device__ float g_xhi[(size_t)N_TOK * HDIM];
__device__ float g_xlo[(size_t)N_TOK * HDIM];
__device__ float g_wthi[(size_t)2560 * HDIM];   // [wi1t(512) | wr1t(1024) | wu1t(1024)] rows n, cols k
__device__ float g_wtlo[(size_t)2560 * HDIM];
__device__ float g_hi[(size_t)N_TOK * 512];
__device__ float g_hr[(size_t)N_TOK * 1024];
__device__ float g_p0[N_TOK], g_p1[N_TOK];
__device__ int   g_e0[N_TOK], g_e1[N_TOK];
__device__ unsigned char g_mask[N_TOK];
__device__ int   g_idx_i[N_TOK], g_idx_u[N_TOK];
__device__ int   g_cnt[2];
__device__ float g_part[512 * 16];

// ================= helpers =================
static __device__ __forceinline__ uint32_t smem_u32(const void* p) {
    uint32_t a;
    asm("{ .reg .u64 t; cvta.to.shared.u64 t, %1; cvt.u32.u64 %0, t; }" : "=r"(a) : "l"(p));
    return a;
}
static __device__ __forceinline__ void cp_async16(uint32_t dst, const void* src) {
    asm volatile("cp.async.cg.shared.global [%0], [%1], 16;" :: "r"(dst), "l"(src));
}
static __device__ __forceinline__ void cp_commit() { asm volatile("cp.async.commit_group;" ::: "memory"); }
static __device__ __forceinline__ void cp_wait1()  { asm volatile("cp.async.wait_group 1;"  ::: "memory"); }

static __device__ __forceinline__ void tf32_split(float v, float& hi, float& lo) {
    uint32_t h;
    asm("cvt.rna.tf32.f32 %0, %1;" : "=r"(h) : "f"(v));
    hi = __uint_as_float(h);
    const float r = v - hi;
    uint32_t l;
    asm("cvt.rna.tf32.f32 %0, %1;" : "=r"(l) : "f"(r));
    lo = __uint_as_float(l);
}

// k-permutation within each 8-group: k -> (k&~7) | ((k&3)<<1) | ((k>>2)&1)
static __device__ __forceinline__ int kperm(int k) {
    return (k & ~7) | (((k & 3) << 1) | ((k >> 2) & 1));
}

// m16n8k8 tf32 mma; a02 = (a0,a2) [row g, k=c / k=c+4], a13 = (a1,a3) [row g+8]
static __device__ __forceinline__ void mma8(float4& d, float2 a02, float2 a13, float2 b) {
    asm volatile(
        "mma.sync.aligned.m16n8k8.row.col.f32.tf32.tf32.f32 "
        "{%0,%1,%2,%3}, {%4,%5,%6,%7}, {%8,%9}, {%0,%1,%2,%3};"
        : "+f"(d.x), "+f"(d.y), "+f"(d.z), "+f"(d.w)
        : "r"(__float_as_uint(a02.x)), "r"(__float_as_uint(a13.x)),
          "r"(__float_as_uint(a02.y)), "r"(__float_as_uint(a13.y)),
          "r"(__float_as_uint(b.x)),   "r"(__float_as_uint(b.y)));
}

// ================= smem layout (dynamic) =================
// [ s_tok int[128] ][ 3 stages x (A_hi 1024f | A_lo 1024f | B_hi 2048f | B_lo 2048f) ]
#define STAGE_F 6144
#define SMEM_TC (512 + 3 * STAGE_F * 4)

// ================= mma GEMM core: out[tok, ncol0:+256] = relu(X@Wt^T + bias) ======
// CTA tile M=128 x N=256, K=1024; warp tile 64x64; 3-stage cp.async pipeline.
__device__ __forceinline__ void gemm_mma_tile(
    const int* __restrict__ tok_list, int row_base, int row_cnt,
    const float* __restrict__ bthi, const float* __restrict__ btlo,
    int ncol0, const float* __restrict__ bias,
    float* __restrict__ outp, int out_ld)
{
    extern __shared__ __align__(16) float smem[];
    int* s_tok = (int*)smem;
    float* stg = smem + 128;
    const int tid = threadIdx.x;
    const int wid = tid >> 5, lane = tid & 31;

    if (tid < 128) {
        const int r = row_base + tid;
        s_tok[tid] = tok_list ? ((r < row_cnt) ? tok_list[r] : -1) : r;
    }
    __syncthreads();

    // ---- per-thread cp.async source/dest precompute ----
    const int r0 = tid >> 1, h = tid & 1;            // A row, 16B half
    int tokA = s_tok[r0]; if (tokA < 0) tokA = 0;
    const float* srcAh = g_xhi + (size_t)tokA * HDIM + h * 4;
    const float* srcAl = g_xlo + (size_t)tokA * HDIM + h * 4;
    const int nB0 = tid >> 1, nB1 = nB0 + 128;
    const float* srcBh0 = bthi + (size_t)(ncol0 + nB0) * HDIM + h * 4;
    const float* srcBh1 = bthi + (size_t)(ncol0 + nB1) * HDIM + h * 4;
    const float* srcBl0 = btlo + (size_t)(ncol0 + nB0) * HDIM + h * 4;
    const float* srcBl1 = btlo + (size_t)(ncol0 + nB1) * HDIM + h * 4;
    const uint32_t sbase = smem_u32(stg);
    const uint32_t dA  = (uint32_t)(r0 * 8 + h * 4) * 4;
    const uint32_t dB0 = (uint32_t)(nB0 * 8 + h * 4) * 4;
    const uint32_t dB1 = (uint32_t)(nB1 * 8 + h * 4) * 4;

    #define ISSUE_STAGE(s) do { \
        const uint32_t _sb = sbase + ((s) % 3) * (STAGE_F * 4); \
        const int _k = (s) * 8; \
        cp_async16(_sb + dA,                  srcAh + _k); \
        cp_async16(_sb + 1024 * 4 + dA,       srcAl + _k); \
        cp_async16(_sb + 2048 * 4 + dB0,      srcBh0 + _k); \
        cp_async16(_sb + 2048 * 4 + dB1,      srcBh1 + _k); \
        cp_async16(_sb + 4096 * 4 + dB0,      srcBl0 + _k); \
        cp_async16(_sb + 4096 * 4 + dB1,      srcBl1 + _k); \
        cp_commit(); \
    } while (0)

    // ---- accumulators ----
    float4 acc[4][8];
#pragma unroll
    for (int mt = 0; mt < 4; mt++)
#pragma unroll
        for (int nt = 0; nt < 8; nt++) acc[mt][nt] = make_float4(0.f, 0.f, 0.f, 0.f);

    const int warpM = (wid & 1) * 64;
    const int warpN = (wid >> 1) * 64;
    const int g = lane >> 2, c = lane & 3;

    ISSUE_STAGE(0);
    ISSUE_STAGE(1);

    for (int s = 0; s < 128; s++) {
        cp_wait1();
        __syncthreads();
        if (s + 2 < 128) ISSUE_STAGE(s + 2);

        const float* sb = stg + (s % 3) * STAGE_F;
        // A fragments (hi & lo): conflict-free LDS.64 thanks to k-permuted layout
        float2 ah02[4], ah13[4], al02[4], al13[4];
#pragma unroll
        for (int mt = 0; mt < 4; mt++) {
            const int rbase = (warpM + mt * 16 + g) * 8 + c * 2;
            ah02[mt] = *(const float2*)(sb + rbase);
            ah13[mt] = *(const float2*)(sb + rbase + 64);
            al02[mt] = *(const float2*)(sb + 1024 + rbase);
            al13[mt] = *(const float2*)(sb + 1024 + rbase + 64);
        }
#pragma unroll
        for (int nt = 0; nt < 8; nt++) {
            const int bbase = (warpN + nt * 8 + g) * 8 + c * 2;
            const float2 bh = *(const float2*)(sb + 2048 + bbase);
            const float2 bl = *(const float2*)(sb + 4096 + bbase);
#pragma unroll
            for (int mt = 0; mt < 4; mt++) {
                mma8(acc[mt][nt], ah02[mt], ah13[mt], bh);
                mma8(acc[mt][nt], ah02[mt], ah13[mt], bl);
                mma8(acc[mt][nt], al02[mt], al13[mt], bh);
            }
        }
        __syncthreads();
    }
    #undef ISSUE_STAGE

    // ---- epilogue: bias + relu, float2 stores ----
#pragma unroll
    for (int mt = 0; mt < 4; mt++) {
        const int rr0 = warpM + mt * 16 + g;
        const int rr1 = rr0 + 8;
        const int tok0 = s_tok[rr0];
        const int tok1 = s_tok[rr1];
#pragma unroll
        for (int nt = 0; nt < 8; nt++) {
            const int col = ncol0 + warpN + nt * 8 + c * 2;
            const float2 bs = *(const float2*)(bias + col);
            if (tok0 >= 0) {
                float2 v;
                v.x = fmaxf(acc[mt][nt].x + bs.x, 0.0f);
                v.y = fmaxf(acc[mt][nt].y + bs.y, 0.0f);
                *(float2*)(outp + (size_t)tok0 * out_ld + col) = v;
            }
            if (tok1 >= 0) {
                float2 v;
                v.x = fmaxf(acc[mt][nt].z + bs.x, 0.0f);
                v.y = fmaxf(acc[mt][nt].w + bs.y, 0.0f);
                *(float2*)(outp + (size_t)tok1 * out_ld + col) = v;
            }
        }
    }
}

// ================= prep: zero part1 + weight transpose/split + X split =============
#define NZ1 96
#define Z1_F4 15728640   // float4 zeroed here (251.7 MB)
#define Z2_F4 9437184    // float4 zeroed in gemmA wave (151 MB)

__global__ __launch_bounds__(256) void prep_kernel(
    const float* __restrict__ x,
    const float* __restrict__ wi1, const float* __restrict__ wr1, const float* __restrict__ wu1,
    float4* __restrict__ zero_base)
{
    const int bx = blockIdx.x;
    const int tid = threadIdx.x;
    if (bx < NZ1) {
        const float4 z = make_float4(0.f, 0.f, 0.f, 0.f);
        for (size_t i = (size_t)bx * 256 + tid; i < (size_t)Z1_F4; i += (size_t)NZ1 * 256)
            zero_base[i] = z;
        return;
    }
    if (bx < NZ1 + 2560) {
        // 32x32 transpose + split tile, k-permuted writes
        __shared__ float s_hi[32][33], s_lo[32][33];
        const int tt = bx - NZ1;
        const float* W; int NC, rowbase, u;
        if (tt < 512)       { W = wi1; NC = 512;  u = tt;        rowbase = (u >> 5) * 32; }
        else if (tt < 1536) { W = wr1; NC = 1024; u = tt - 512;  rowbase = 512  + (u >> 5) * 32; }
        else                { W = wu1; NC = 1024; u = tt - 1536; rowbase = 1536 + (u >> 5) * 32; }
        const int tk = (u & 31) * 32;
        const int nt = ((u >> 5) * 32) % ((W == wi1) ? 512 : 1024);
        const int tx = tid & 31, ty = tid >> 5;
#pragma unroll
        for (int y4 = 0; y4 < 4; y4++) {
            const int y = ty + y4 * 8;
            const float v = W[(size_t)(tk + y) * NC + nt + tx];
            float hh, ll; tf32_split(v, hh, ll);
            s_hi[y][tx] = hh; s_lo[y][tx] = ll;
        }
        __syncthreads();
#pragma unroll
        for (int y4 = 0; y4 < 4; y4++) {
            const int y = ty + y4 * 8;
            const int kp = kperm(tk + tx);
            g_wthi[(size_t)(rowbase + y) * HDIM + kp] = s_hi[tx][y];
            g_wtlo[(size_t)(rowbase + y) * HDIM + kp] = s_lo[tx][y];
        }
        return;
    }
    // X split with k-permutation: 512 CTAs x 2048 float4
    {
        const int xi = bx - (NZ1 + 2560);
        const float4* xs = (const float4*)x;
#pragma unroll
        for (int p = 0; p < 8; p++) {
            const size_t i = (size_t)xi * 2048 + p * 256 + tid;
            const float4 v = xs[i];
            float4 hh, ll;
            tf32_split(v.x, hh.x, ll.x);
            tf32_split(v.y, hh.y, ll.y);
            tf32_split(v.z, hh.z, ll.z);
            tf32_split(v.w, hh.w, ll.w);
            const size_t kf = i * 4;                           // global float index
            const size_t d0 = (kf & ~(size_t)7) + ((kf >> 2) & 1);
            g_xhi[d0] = hh.x; g_xhi[d0 + 2] = hh.y; g_xhi[d0 + 4] = hh.z; g_xhi[d0 + 6] = hh.w;
            g_xlo[d0] = ll.x; g_xlo[d0 + 2] = ll.y; g_xlo[d0 + 4] = ll.z; g_xlo[d0 + 6] = ll.w;
        }
    }
}

// ================= gemmA wave: 64 mma CTAs + 84 zero CTAs ==========================
__global__ __launch_bounds__(256, 1) void gemmA_tc(const float* __restrict__ bi1,
                                                   float4* __restrict__ zero_base) {
    const int bx = blockIdx.x;
    if (bx >= 64) {
        const int z = bx - 64;
        const float4 zz = make_float4(0.f, 0.f, 0.f, 0.f);
        for (size_t i = (size_t)z * 256 + threadIdx.x; i < (size_t)Z2_F4; i += (size_t)84 * 256)
            zero_base[(size_t)Z1_F4 + i] = zz;
        return;
    }
    const int ncol0 = (bx & 1) * 256;
    const int m0    = (bx >> 1) * 128;
    gemm_mma_tile(nullptr, m0, N_TOK, g_wthi, g_wtlo, ncol0, bi1, g_hi, 512);
}

// ================= gemmC: gathered router GEMM =====================================
__global__ __launch_bounds__(256, 1) void gemmC_tc(const float* __restrict__ br1,
                                                   const float* __restrict__ bu1) {
    const int ci = g_cnt[0], cu = g_cnt[1];
    const int ti = (ci + 127) >> 7;
    const int tu = (cu + 127) >> 7;
    const int by = blockIdx.y;
    if (by >= ti + tu) return;
    const float* bias; const int* list; int base, cnt; size_t wrow;
    if (by < ti) { bias = br1; list = g_idx_i; base = by << 7;        cnt = ci; wrow = 512;  }
    else         { bias = bu1; list = g_idx_u; base = (by - ti) << 7; cnt = cu; wrow = 1536; }
    gemm_mma_tile(list, base, cnt,
                  g_wthi + wrow * HDIM, g_wtlo + wrow * HDIM,
                  blockIdx.x * 256, bias, g_hr, 1024);
}

// ================= importance: dot(g_hi, wi2) + sigmoid gate =======================
__global__ void importance_kernel(const float* __restrict__ wi2, const float* __restrict__ bi2,
                                  float* __restrict__ out_imp) {
    const int gt   = (blockIdx.x * blockDim.x + threadIdx.x) >> 5;
    const int lane = threadIdx.x & 31;
    if (gt >= N_TOK) return;
    const float* hr = g_hi + (size_t)gt * 512;
    float z = 0.0f;
    for (int j = lane; j < 512; j += 32) z = fmaf(hr[j], wi2[j], z);
#pragma unroll
    for (int off = 16; off > 0; off >>= 1) z += __shfl_xor_sync(0xffffffffu, z, off);
    if (lane == 0) {
        z += bi2[0];
        const float sig = 1.0f / (1.0f + expf(-z));
        out_imp[gt] = sig;
        g_mask[gt] = (sig > 0.5f) ? 1 : 0;
    }
}

// ================= compaction ======================================================
__global__ void compact_kernel() {
    __shared__ int wcnt_i[32], wcnt_u[32], wpre_i[32], wpre_u[32];
    __shared__ int base_i, base_u;
    const int tid = threadIdx.x, lane = tid & 31, warp = tid >> 5;
    if (tid == 0) { base_i = 0; base_u = 0; }
    __syncthreads();
    for (int cc = 0; cc < 4; cc++) {
        const int t = cc * 1024 + tid;
        const int m = g_mask[t];
        const unsigned bi = __ballot_sync(0xffffffffu, m);
        const unsigned lt = (1u << lane) - 1u;
        if (lane == 0) { wcnt_i[warp] = __popc(bi); wcnt_u[warp] = 32 - __popc(bi); }
        __syncthreads();
        if (tid == 0) {
            int si = base_i, su = base_u;
            for (int w = 0; w < 32; w++) {
                wpre_i[w] = si; si += wcnt_i[w];
                wpre_u[w] = su; su += wcnt_u[w];
            }
            base_i = si; base_u = su;
        }
        __syncthreads();
        if (m) g_idx_i[wpre_i[warp] + __popc(bi & lt)] = t;
        else   g_idx_u[wpre_u[warp] + __popc(~bi & lt)] = t;
        __syncthreads();
    }
    if (tid == 0) { g_cnt[0] = base_i; g_cnt[1] = base_u; }
}

// ================= routing: layer 2 + softmax + top-2 + aux partials ===============
__global__ void routing_kernel(const float* __restrict__ wr2, const float* __restrict__ br2,
                               const float* __restrict__ wu2, const float* __restrict__ bu2,
                               float* __restrict__ out_probs) {
    __shared__ float s_aux[8][16];
    const int gt   = (blockIdx.x * blockDim.x + threadIdx.x) >> 5;
    const int lane = threadIdx.x & 31;
    const int warp = threadIdx.x >> 5;
    if (gt < N_TOK) {
        const bool m = g_mask[gt] != 0;
        const float* hs = g_hr + (size_t)gt * 1024;
        const float* W2 = m ? wr2 : wu2;
        const float* b2 = m ? br2 : bu2;
        float acc[NE];
#pragma unroll
        for (int e = 0; e < NE; e++) acc[e] = 0.0f;
        for (int j = lane; j < 1024; j += 32) {
            const float hv = hs[j];
            float4 w0 = *(const float4*)(W2 + (size_t)j * 8);
            float4 w1 = *(const float4*)(W2 + (size_t)j * 8 + 4);
            acc[0] = fmaf(hv, w0.x, acc[0]);
            acc[1] = fmaf(hv, w0.y, acc[1]);
            acc[2] = fmaf(hv, w0.z, acc[2]);
            acc[3] = fmaf(hv, w0.w, acc[3]);
            acc[4] = fmaf(hv, w1.x, acc[4]);
            acc[5] = fmaf(hv, w1.y, acc[5]);
            acc[6] = fmaf(hv, w1.z, acc[6]);
            acc[7] = fmaf(hv, w1.w, acc[7]);
        }
#pragma unroll
        for (int off = 16; off > 0; off >>= 1)
#pragma unroll
            for (int e = 0; e < NE; e++) acc[e] += __shfl_xor_sync(0xffffffffu, acc[e], off);

        if (lane == 0) {
            float l[NE], pr[NE];
            float mx = -1e30f;
#pragma unroll
            for (int e = 0; e < NE; e++) { l[e] = acc[e] + b2[e]; mx = fmaxf(mx, l[e]); }
            float sum = 0.0f;
#pragma unroll
            for (int e = 0; e < NE; e++) { pr[e] = expf(l[e] - mx); sum += pr[e]; }
            const float inv = 1.0f / sum;
            const float mf = m ? 1.0f : 0.0f;
#pragma unroll
            for (int e = 0; e < NE; e++) {
                pr[e] *= inv;
                out_probs[(size_t)gt * NE + e] = pr[e];
                s_aux[warp][e]      = pr[e];
                s_aux[warp][NE + e] = pr[e] * mf;
            }
            int e0 = 0; float p0v = pr[0];
#pragma unroll
            for (int e = 1; e < NE; e++) if (pr[e] > p0v) { p0v = pr[e]; e0 = e; }
            int e1 = -1; float p1v = -1.0f;
#pragma unroll
            for (int e = 0; e < NE; e++) if (e != e0 && pr[e] > p1v) { p1v = pr[e]; e1 = e; }
            const float sn = p0v + p1v;
            g_e0[gt] = e0; g_e1[gt] = e1;
            g_p0[gt] = p0v / sn; g_p1[gt] = p1v / sn;
        }
    }
    __syncthreads();
    if (threadIdx.x < 16) {
        float s = 0.0f;
        for (int w = 0; w < 8; w++) s += s_aux[w][threadIdx.x];
        g_part[(size_t)blockIdx.x * 16 + threadIdx.x] = s;
    }
}

// ================= dispatch (block 0) + aux loss (block 1) =========================
__global__ void dispatch_aux_kernel(float* __restrict__ disp, float* __restrict__ comb,
                                    float* __restrict__ out_aux) {
    const int tid = threadIdx.x;
    if (blockIdx.x == 0) {
        __shared__ int base[NE];
        __shared__ int whist[32][NE];
        __shared__ int wpref[32][NE];
        const int lane = tid & 31, warp = tid >> 5;
        if (tid < NE) base[tid] = 0;
        __syncthreads();
        for (int chunk = 0; chunk < 8; chunk++) {
            const int i = chunk * 1024 + tid;
            const int k = i >> 12;
            const int t = i & (N_TOK - 1);
            const int e   = (k == 0) ? g_e0[t] : g_e1[t];
            const float p = (k == 0) ? g_p0[t] : g_p1[t];

            if (lane < NE) whist[warp][lane] = 0;
            __syncwarp();
            const unsigned mm  = __match_any_sync(0xffffffffu, e);
            const unsigned blo = mm & ((1u << lane) - 1u);
            const int rank = __popc(blo);
            if (blo == 0u) whist[warp][e] = __popc(mm);
            __syncthreads();

            if (tid < NE) {
                int s = base[tid];
                for (int w = 0; w < 32; w++) { wpref[w][tid] = s; s += whist[w][tid]; }
                base[tid] = s;
            }
            __syncthreads();

            const int pos = wpref[warp][e] + rank;
            if (pos < CAP) {
                const size_t idx = ((size_t)t * NE + e) * CAP + pos;
                disp[idx] = 1.0f;
                comb[idx] = p;
            }
            __syncthreads();
        }
    } else {
        __shared__ float sm[512][16];
        if (tid < 512) {
#pragma unroll
            for (int v = 0; v < 16; v++) sm[tid][v] = g_part[(size_t)tid * 16 + v];
        }
        __syncthreads();
        for (int s = 256; s > 0; s >>= 1) {
            if (tid < s)
#pragma unroll
                for (int v = 0; v < 16; v++) sm[tid][v] += sm[tid + s][v];
            __syncthreads();
        }
        if (tid == 0) {
            float ent = 0.0f;
#pragma unroll
            for (int e = 0; e < NE; e++) {
                const float r = sm[0][e] / (float)N_TOK;
                ent += r * logf(r * 8.0f + 1e-9f);
            }
            float tot = 0.0f;
            float SI[NE];
#pragma unroll
            for (int e = 0; e < NE; e++) { SI[e] = sm[0][NE + e] + 1e-9f; tot += SI[e]; }
            float ie = 0.0f;
#pragma unroll
            for (int e = 0; e < NE; e++) {
                const float ip = SI[e] / tot;
                ie -= ip * logf(ip + 1e-9f);
            }
            out_aux[0] = ent - 0.1f * (ie / logf(8.0f));
        }
    }
}

// ================= launch ==========================================================
extern "C" void kernel_launch(void* const* d_in, const int* in_sizes, int n_in,
                              void* d_out, int out_size) {
    const float* x   = (const float*)d_in[0];
    const float* wi1 = (const float*)d_in[1];
    const float* bi1 = (const float*)d_in[2];
    const float* wi2 = (const float*)d_in[3];
    const float* bi2 = (const float*)d_in[4];
    const float* wr1 = (const float*)d_in[5];
    const float* br1 = (const float*)d_in[6];
    const float* wr2 = (const float*)d_in[7];
    const float* br2 = (const float*)d_in[8];
    const float* wu1 = (const float*)d_in[9];
    const float* bu1 = (const float*)d_in[10];
    const float* wu2 = (const float*)d_in[11];
    const float* bu2 = (const float*)d_in[12];

    float* out   = (float*)d_out;
    float* disp  = out;                                   // [4096, 8, 1536]
    float* comb  = disp + (size_t)N_TOK * NE * CAP;       // [4096, 8, 1536]
    float* probs = comb + (size_t)N_TOK * NE * CAP;       // [4096, 8]
    float* aux   = probs + (size_t)N_TOK * NE;            // [1]
    float* imp   = aux + 1;                               // [4096]

    cudaFuncSetAttribute(gemmA_tc, cudaFuncAttributeMaxDynamicSharedMemorySize, SMEM_TC);
    cudaFuncSetAttribute(gemmC_tc, cudaFuncAttributeMaxDynamicSharedMemorySize, SMEM_TC);

    prep_kernel<<<NZ1 + 2560 + 512, 256>>>(x, wi1, wr1, wu1, (float4*)disp);
    gemmA_tc<<<148, 256, SMEM_TC>>>(bi1, (float4*)disp);
    importance_kernel<<<512, 256>>>(wi2, bi2, imp);
    compact_kernel<<<1, 1024>>>();
    gemmC_tc<<<dim3(4, 34), 256, SMEM_TC>>>(br1, bu1);
    routing_kernel<<<512, 256>>>(wr2, br2, wu2, bu2, probs);
    dispatch_aux_kernel<<<2, 1024>>>(disp, comb, aux);
}

// round 6
// speedup vs baseline: 1.1495x; 1.1495x over previous
#include <cuda_runtime.h>
#include <cstdint>
#include <cstddef>

#define N_TOK 4096
#define HDIM  1024
#define NE    8
#define CAP   1536

// ---------------- scratch (static device globals: no allocation) ----------------
// X and Wt stored tf32-split AND k-permuted within each 8-group: order [0,4,1,5,2,6,3,7]
__device__ float g_xhi[(size_t)N_TOK * HDIM];
__device__ float g_xlo[(size_t)N_TOK * HDIM];
__device__ float g_wthi[(size_t)2560 * HDIM];   // [wi1t(512) | wr1t(1024) | wu1t(1024)] rows n, cols k
__device__ float g_wtlo[(size_t)2560 * HDIM];
__device__ float g_hi[(size_t)N_TOK * 512];
__device__ float g_hr[(size_t)N_TOK * 1024];
__device__ float g_p0[N_TOK], g_p1[N_TOK];
__device__ int   g_e0[N_TOK], g_e1[N_TOK];
__device__ unsigned char g_mask[N_TOK];
__device__ int   g_idx_i[N_TOK], g_idx_u[N_TOK];
__device__ int   g_cnt[2];
__device__ float g_part[512 * 16];

// ================= helpers =================
static __device__ __forceinline__ uint32_t smem_u32(const void* p) {
    uint32_t a;
    asm("{ .reg .u64 t; cvta.to.shared.u64 t, %1; cvt.u32.u64 %0, t; }" : "=r"(a) : "l"(p));
    return a;
}
static __device__ __forceinline__ void cp_async16(uint32_t dst, const void* src) {
    asm volatile("cp.async.cg.shared.global [%0], [%1], 16;" :: "r"(dst), "l"(src));
}
static __device__ __forceinline__ void cp_commit() { asm volatile("cp.async.commit_group;" ::: "memory"); }
static __device__ __forceinline__ void cp_wait1()  { asm volatile("cp.async.wait_group 1;"  ::: "memory"); }
static __device__ __forceinline__ void cp_wait0()  { asm volatile("cp.async.wait_group 0;"  ::: "memory"); }

static __device__ __forceinline__ void tf32_split(float v, float& hi, float& lo) {
    uint32_t h;
    asm("cvt.rna.tf32.f32 %0, %1;" : "=r"(h) : "f"(v));
    hi = __uint_as_float(h);
    const float r = v - hi;
    uint32_t l;
    asm("cvt.rna.tf32.f32 %0, %1;" : "=r"(l) : "f"(r));
    lo = __uint_as_float(l);
}

// k-permutation within each 8-group: k -> (k&~7) | ((k&3)<<1) | ((k>>2)&1)
static __device__ __forceinline__ int kperm(int k) {
    return (k & ~7) | (((k & 3) << 1) | ((k >> 2) & 1));
}

// m16n8k8 tf32 mma
static __device__ __forceinline__ void mma8(float4& d, float2 a02, float2 a13, float2 b) {
    asm volatile(
        "mma.sync.aligned.m16n8k8.row.col.f32.tf32.tf32.f32 "
        "{%0,%1,%2,%3}, {%4,%5,%6,%7}, {%8,%9}, {%0,%1,%2,%3};"
        : "+f"(d.x), "+f"(d.y), "+f"(d.z), "+f"(d.w)
        : "r"(__float_as_uint(a02.x)), "r"(__float_as_uint(a13.x)),
          "r"(__float_as_uint(a02.y)), "r"(__float_as_uint(a13.y)),
          "r"(__float_as_uint(b.x)),   "r"(__float_as_uint(b.y)));
}

// ================= mma GEMM core =================
// CTA tile M_TILE x 256, K=1024 in 32 stages of K=32; 2-buffer cp.async pipeline.
// Stage smem layout (floats): [Ahi A_F][Alo A_F][Bhi 8192][Blo 8192],
// each region holds 4 k8 sub-chunks: sub c at c*(rows*8), row r at r*8 (k-permuted).
template <int M_TILE>
__device__ __forceinline__ void gemm_mma_tile(
    const int* __restrict__ tok_list, int row_base, int row_cnt,
    const float* __restrict__ bthi, const float* __restrict__ btlo,
    int ncol0, const float* __restrict__ bias,
    float* __restrict__ outp, int out_ld)
{
    constexpr int A_F    = M_TILE * 32;          // floats per A matrix per stage
    constexpr int B_F    = 256 * 32;             // 8192
    constexpr int STG_F  = 2 * A_F + 2 * B_F;
    constexpr int NP_A   = A_F / 4 / 256;        // f4 passes for A (per hi/lo)
    constexpr int NP_B   = B_F / 4 / 256;        // 8
    constexpr int WM     = M_TILE / 2;
    constexpr int MT     = WM / 16;              // m16 frags per warp

    extern __shared__ __align__(16) float smem[];
    int* s_tok = (int*)smem;
    float* stg = smem + 128;
    const int tid = threadIdx.x;
    const int wid = tid >> 5, lane = tid & 31;

    if (tid < M_TILE) {
        const int r = row_base + tid;
        s_tok[tid] = tok_list ? ((r < row_cnt) ? tok_list[r] : -1) : r;
    }
    __syncthreads();

    // ---- per-thread cp.async source pointers / dest offsets (per pass) ----
    const uint32_t sbase = smem_u32(stg);
    const float* srcAh[NP_A]; const float* srcAl[NP_A]; uint32_t dstA[NP_A];
#pragma unroll
    for (int p = 0; p < NP_A; p++) {
        const int i = tid + p * 256;
        const int r = i >> 3, j = i & 7;
        const int c = j >> 1, h = j & 1;
        int tok = s_tok[r]; if (tok < 0) tok = 0;
        srcAh[p] = g_xhi + (size_t)tok * HDIM + c * 8 + h * 4;
        srcAl[p] = g_xlo + (size_t)tok * HDIM + c * 8 + h * 4;
        dstA[p]  = (uint32_t)(c * (M_TILE * 8) + r * 8 + h * 4) * 4;
    }
    const float* srcBh[NP_B]; const float* srcBl[NP_B]; uint32_t dstB[NP_B];
#pragma unroll
    for (int p = 0; p < NP_B; p++) {
        const int i = tid + p * 256;
        const int r = i >> 3, j = i & 7;
        const int c = j >> 1, h = j & 1;
        srcBh[p] = bthi + (size_t)(ncol0 + r) * HDIM + c * 8 + h * 4;
        srcBl[p] = btlo + (size_t)(ncol0 + r) * HDIM + c * 8 + h * 4;
        dstB[p]  = (uint32_t)(c * (256 * 8) + r * 8 + h * 4) * 4;
    }

    #define ISSUE_STAGE(s) do { \
        const uint32_t _sb = sbase + ((s) & 1) * (STG_F * 4); \
        const int _k = (s) * 32; \
        _Pragma("unroll") \
        for (int p = 0; p < NP_A; p++) { \
            cp_async16(_sb + dstA[p],             srcAh[p] + _k); \
            cp_async16(_sb + A_F * 4 + dstA[p],   srcAl[p] + _k); \
        } \
        _Pragma("unroll") \
        for (int p = 0; p < NP_B; p++) { \
            cp_async16(_sb + 2 * A_F * 4 + dstB[p],           srcBh[p] + _k); \
            cp_async16(_sb + (2 * A_F + B_F) * 4 + dstB[p],   srcBl[p] + _k); \
        } \
        cp_commit(); \
    } while (0)

    float4 acc[MT][8];
#pragma unroll
    for (int mt = 0; mt < MT; mt++)
#pragma unroll
        for (int nt = 0; nt < 8; nt++) acc[mt][nt] = make_float4(0.f, 0.f, 0.f, 0.f);

    const int warpM = (wid & 1) * WM;
    const int warpN = (wid >> 1) * 64;
    const int g = lane >> 2, c = lane & 3;

    ISSUE_STAGE(0);
    ISSUE_STAGE(1);

    for (int s = 0; s < 32; s++) {
        if (s >= 30) cp_wait0(); else cp_wait1();
        __syncthreads();

        const float* sb = stg + (s & 1) * STG_F;
#pragma unroll
        for (int c4 = 0; c4 < 4; c4++) {
            const float* sA = sb + c4 * (M_TILE * 8);
            const float* sB = sb + 2 * A_F + c4 * (256 * 8);
            float2 ah02[MT], ah13[MT], al02[MT], al13[MT];
#pragma unroll
            for (int mt = 0; mt < MT; mt++) {
                const int rbase = (warpM + mt * 16 + g) * 8 + c * 2;
                ah02[mt] = *(const float2*)(sA + rbase);
                ah13[mt] = *(const float2*)(sA + rbase + 64);
                al02[mt] = *(const float2*)(sA + A_F + rbase);
                al13[mt] = *(const float2*)(sA + A_F + rbase + 64);
            }
#pragma unroll
            for (int nt = 0; nt < 8; nt++) {
                const int bbase = (warpN + nt * 8 + g) * 8 + c * 2;
                const float2 bh = *(const float2*)(sB + bbase);
                const float2 bl = *(const float2*)(sB + B_F + bbase);
#pragma unroll
                for (int mt = 0; mt < MT; mt++) {
                    mma8(acc[mt][nt], ah02[mt], ah13[mt], bh);
                    mma8(acc[mt][nt], ah02[mt], ah13[mt], bl);
                    mma8(acc[mt][nt], al02[mt], al13[mt], bh);
                }
            }
        }
        __syncthreads();
        if (s + 2 < 32) ISSUE_STAGE(s + 2);
    }
    #undef ISSUE_STAGE

    // ---- epilogue: bias + relu, float2 stores ----
#pragma unroll
    for (int mt = 0; mt < MT; mt++) {
        const int rr0 = warpM + mt * 16 + g;
        const int rr1 = rr0 + 8;
        const int tok0 = s_tok[rr0];
        const int tok1 = s_tok[rr1];
#pragma unroll
        for (int nt = 0; nt < 8; nt++) {
            const int col = ncol0 + warpN + nt * 8 + c * 2;
            const float2 bs = *(const float2*)(bias + col);
            if (tok0 >= 0) {
                float2 v;
                v.x = fmaxf(acc[mt][nt].x + bs.x, 0.0f);
                v.y = fmaxf(acc[mt][nt].y + bs.y, 0.0f);
                *(float2*)(outp + (size_t)tok0 * out_ld + col) = v;
            }
            if (tok1 >= 0) {
                float2 v;
                v.x = fmaxf(acc[mt][nt].z + bs.x, 0.0f);
                v.y = fmaxf(acc[mt][nt].w + bs.y, 0.0f);
                *(float2*)(outp + (size_t)tok1 * out_ld + col) = v;
            }
        }
    }
}

#define STG_F_64  (2 * 64 * 32 + 2 * 8192)    // 20480
#define STG_F_128 (2 * 128 * 32 + 2 * 8192)   // 24576
#define SMEM_A_TC (512 + 2 * STG_F_64 * 4)    // 164352
#define SMEM_C_TC (512 + 2 * STG_F_128 * 4)   // 197120

// ================= prep: zero part1 + weight transpose/split + X split =============
#define NZ1 96
#define Z1_F4 23068672   // float4 zeroed here (369 MB)
#define Z2_F4 2097152    // float4 zeroed in gemmA wave (33.5 MB)

__global__ __launch_bounds__(256) void prep_kernel(
    const float* __restrict__ x,
    const float* __restrict__ wi1, const float* __restrict__ wr1, const float* __restrict__ wu1,
    float4* __restrict__ zero_base)
{
    const int bx = blockIdx.x;
    const int tid = threadIdx.x;
    if (bx < NZ1) {
        const float4 z = make_float4(0.f, 0.f, 0.f, 0.f);
        for (size_t i = (size_t)bx * 256 + tid; i < (size_t)Z1_F4; i += (size_t)NZ1 * 256)
            zero_base[i] = z;
        return;
    }
    if (bx < NZ1 + 2560) {
        __shared__ float s_hi[32][33], s_lo[32][33];
        const int tt = bx - NZ1;
        const float* W; int NC, rowbase, u;
        if (tt < 512)       { W = wi1; NC = 512;  u = tt;        rowbase = (u >> 5) * 32; }
        else if (tt < 1536) { W = wr1; NC = 1024; u = tt - 512;  rowbase = 512  + (u >> 5) * 32; }
        else                { W = wu1; NC = 1024; u = tt - 1536; rowbase = 1536 + (u >> 5) * 32; }
        const int tk = (u & 31) * 32;
        const int nt = ((u >> 5) * 32) % ((W == wi1) ? 512 : 1024);
        const int tx = tid & 31, ty = tid >> 5;
#pragma unroll
        for (int y4 = 0; y4 < 4; y4++) {
            const int y = ty + y4 * 8;
            const float v = W[(size_t)(tk + y) * NC + nt + tx];
            float hh, ll; tf32_split(v, hh, ll);
            s_hi[y][tx] = hh; s_lo[y][tx] = ll;
        }
        __syncthreads();
#pragma unroll
        for (int y4 = 0; y4 < 4; y4++) {
            const int y = ty + y4 * 8;
            const int kp = kperm(tk + tx);
            g_wthi[(size_t)(rowbase + y) * HDIM + kp] = s_hi[tx][y];
            g_wtlo[(size_t)(rowbase + y) * HDIM + kp] = s_lo[tx][y];
        }
        return;
    }
    // X split with k-permutation: 512 CTAs x 2048 float4
    {
        const int xi = bx - (NZ1 + 2560);
        const float4* xs = (const float4*)x;
#pragma unroll
        for (int p = 0; p < 8; p++) {
            const size_t i = (size_t)xi * 2048 + p * 256 + tid;
            const float4 v = xs[i];
            float4 hh, ll;
            tf32_split(v.x, hh.x, ll.x);
            tf32_split(v.y, hh.y, ll.y);
            tf32_split(v.z, hh.z, ll.z);
            tf32_split(v.w, hh.w, ll.w);
            const size_t kf = i * 4;
            const size_t d0 = (kf & ~(size_t)7) + ((kf >> 2) & 1);
            g_xhi[d0] = hh.x; g_xhi[d0 + 2] = hh.y; g_xhi[d0 + 4] = hh.z; g_xhi[d0 + 6] = hh.w;
            g_xlo[d0] = ll.x; g_xlo[d0 + 2] = ll.y; g_xlo[d0 + 4] = ll.z; g_xlo[d0 + 6] = ll.w;
        }
    }
}

// ================= gemmA wave: 128 mma CTAs (M64xN256) + 20 zero CTAs ==============
__global__ __launch_bounds__(256, 1) void gemmA_tc(const float* __restrict__ bi1,
                                                   float4* __restrict__ zero_base) {
    const int bx = blockIdx.x;
    if (bx >= 128) {
        const int z = bx - 128;
        const float4 zz = make_float4(0.f, 0.f, 0.f, 0.f);
        for (size_t i = (size_t)z * 256 + threadIdx.x; i < (size_t)Z2_F4; i += (size_t)20 * 256)
            zero_base[(size_t)Z1_F4 + i] = zz;
        return;
    }
    const int ncol0 = (bx & 1) * 256;
    const int m0    = (bx >> 1) * 64;
    gemm_mma_tile<64>(nullptr, m0, N_TOK, g_wthi, g_wtlo, ncol0, bi1, g_hi, 512);
}

// ================= gemmC: gathered router GEMM (M128xN256) =========================
__global__ __launch_bounds__(256, 1) void gemmC_tc(const float* __restrict__ br1,
                                                   const float* __restrict__ bu1) {
    const int ci = g_cnt[0], cu = g_cnt[1];
    const int ti = (ci + 127) >> 7;
    const int tu = (cu + 127) >> 7;
    const int by = blockIdx.y;
    if (by >= ti + tu) return;
    const float* bias; const int* list; int base, cnt; size_t wrow;
    if (by < ti) { bias = br1; list = g_idx_i; base = by << 7;        cnt = ci; wrow = 512;  }
    else         { bias = bu1; list = g_idx_u; base = (by - ti) << 7; cnt = cu; wrow = 1536; }
    gemm_mma_tile<128>(list, base, cnt,
                       g_wthi + wrow * HDIM, g_wtlo + wrow * HDIM,
                       blockIdx.x * 256, bias, g_hr, 1024);
}

// ================= importance: dot(g_hi, wi2) + sigmoid gate =======================
__global__ void importance_kernel(const float* __restrict__ wi2, const float* __restrict__ bi2,
                                  float* __restrict__ out_imp) {
    const int gt   = (blockIdx.x * blockDim.x + threadIdx.x) >> 5;
    const int lane = threadIdx.x & 31;
    if (gt >= N_TOK) return;
    const float* hr = g_hi + (size_t)gt * 512;
    float z = 0.0f;
    for (int j = lane; j < 512; j += 32) z = fmaf(hr[j], wi2[j], z);
#pragma unroll
    for (int off = 16; off > 0; off >>= 1) z += __shfl_xor_sync(0xffffffffu, z, off);
    if (lane == 0) {
        z += bi2[0];
        const float sig = 1.0f / (1.0f + expf(-z));
        out_imp[gt] = sig;
        g_mask[gt] = (sig > 0.5f) ? 1 : 0;
    }
}

// ================= compaction ======================================================
__global__ void compact_kernel() {
    __shared__ int wcnt_i[32], wcnt_u[32], wpre_i[32], wpre_u[32];
    __shared__ int base_i, base_u;
    const int tid = threadIdx.x, lane = tid & 31, warp = tid >> 5;
    if (tid == 0) { base_i = 0; base_u = 0; }
    __syncthreads();
    for (int cc = 0; cc < 4; cc++) {
        const int t = cc * 1024 + tid;
        const int m = g_mask[t];
        const unsigned bi = __ballot_sync(0xffffffffu, m);
        const unsigned lt = (1u << lane) - 1u;
        if (lane == 0) { wcnt_i[warp] = __popc(bi); wcnt_u[warp] = 32 - __popc(bi); }
        __syncthreads();
        if (tid == 0) {
            int si = base_i, su = base_u;
            for (int w = 0; w < 32; w++) {
                wpre_i[w] = si; si += wcnt_i[w];
                wpre_u[w] = su; su += wcnt_u[w];
            }
            base_i = si; base_u = su;
        }
        __syncthreads();
        if (m) g_idx_i[wpre_i[warp] + __popc(bi & lt)] = t;
        else   g_idx_u[wpre_u[warp] + __popc(~bi & lt)] = t;
        __syncthreads();
    }
    if (tid == 0) { g_cnt[0] = base_i; g_cnt[1] = base_u; }
}

// ================= routing: layer 2 + softmax + top-2 + aux partials ===============
__global__ void routing_kernel(const float* __restrict__ wr2, const float* __restrict__ br2,
                               const float* __restrict__ wu2, const float* __restrict__ bu2,
                               float* __restrict__ out_probs) {
    __shared__ float s_aux[8][16];
    const int gt   = (blockIdx.x * blockDim.x + threadIdx.x) >> 5;
    const int lane = threadIdx.x & 31;
    const int warp = threadIdx.x >> 5;
    if (gt < N_TOK) {
        const bool m = g_mask[gt] != 0;
        const float* hs = g_hr + (size_t)gt * 1024;
        const float* W2 = m ? wr2 : wu2;
        const float* b2 = m ? br2 : bu2;
        float acc[NE];
#pragma unroll
        for (int e = 0; e < NE; e++) acc[e] = 0.0f;
        for (int j = lane; j < 1024; j += 32) {
            const float hv = hs[j];
            float4 w0 = *(const float4*)(W2 + (size_t)j * 8);
            float4 w1 = *(const float4*)(W2 + (size_t)j * 8 + 4);
            acc[0] = fmaf(hv, w0.x, acc[0]);
            acc[1] = fmaf(hv, w0.y, acc[1]);
            acc[2] = fmaf(hv, w0.z, acc[2]);
            acc[3] = fmaf(hv, w0.w, acc[3]);
            acc[4] = fmaf(hv, w1.x, acc[4]);
            acc[5] = fmaf(hv, w1.y, acc[5]);
            acc[6] = fmaf(hv, w1.z, acc[6]);
            acc[7] = fmaf(hv, w1.w, acc[7]);
        }
#pragma unroll
        for (int off = 16; off > 0; off >>= 1)
#pragma unroll
            for (int e = 0; e < NE; e++) acc[e] += __shfl_xor_sync(0xffffffffu, acc[e], off);

        if (lane == 0) {
            float l[NE], pr[NE];
            float mx = -1e30f;
#pragma unroll
            for (int e = 0; e < NE; e++) { l[e] = acc[e] + b2[e]; mx = fmaxf(mx, l[e]); }
            float sum = 0.0f;
#pragma unroll
            for (int e = 0; e < NE; e++) { pr[e] = expf(l[e] - mx); sum += pr[e]; }
            const float inv = 1.0f / sum;
            const float mf = m ? 1.0f : 0.0f;
#pragma unroll
            for (int e = 0; e < NE; e++) {
                pr[e] *= inv;
                out_probs[(size_t)gt * NE + e] = pr[e];
                s_aux[warp][e]      = pr[e];
                s_aux[warp][NE + e] = pr[e] * mf;
            }
            int e0 = 0; float p0v = pr[0];
#pragma unroll
            for (int e = 1; e < NE; e++) if (pr[e] > p0v) { p0v = pr[e]; e0 = e; }
            int e1 = -1; float p1v = -1.0f;
#pragma unroll
            for (int e = 0; e < NE; e++) if (e != e0 && pr[e] > p1v) { p1v = pr[e]; e1 = e; }
            const float sn = p0v + p1v;
            g_e0[gt] = e0; g_e1[gt] = e1;
            g_p0[gt] = p0v / sn; g_p1[gt] = p1v / sn;
        }
    }
    __syncthreads();
    if (threadIdx.x < 16) {
        float s = 0.0f;
        for (int w = 0; w < 8; w++) s += s_aux[w][threadIdx.x];
        g_part[(size_t)blockIdx.x * 16 + threadIdx.x] = s;
    }
}

// ================= dispatch (block 0) + aux loss (block 1) =========================
__global__ void dispatch_aux_kernel(float* __restrict__ disp, float* __restrict__ comb,
                                    float* __restrict__ out_aux) {
    const int tid = threadIdx.x;
    if (blockIdx.x == 0) {
        __shared__ int base[NE];
        __shared__ int whist[32][NE];
        __shared__ int wpref[32][NE];
        const int lane = tid & 31, warp = tid >> 5;
        if (tid < NE) base[tid] = 0;
        __syncthreads();
        for (int chunk = 0; chunk < 8; chunk++) {
            const int i = chunk * 1024 + tid;
            const int k = i >> 12;
            const int t = i & (N_TOK - 1);
            const int e   = (k == 0) ? g_e0[t] : g_e1[t];
            const float p = (k == 0) ? g_p0[t] : g_p1[t];

            if (lane < NE) whist[warp][lane] = 0;
            __syncwarp();
            const unsigned mm  = __match_any_sync(0xffffffffu, e);
            const unsigned blo = mm & ((1u << lane) - 1u);
            const int rank = __popc(blo);
            if (blo == 0u) whist[warp][e] = __popc(mm);
            __syncthreads();

            if (tid < NE) {
                int s = base[tid];
                for (int w = 0; w < 32; w++) { wpref[w][tid] = s; s += whist[w][tid]; }
                base[tid] = s;
            }
            __syncthreads();

            const int pos = wpref[warp][e] + rank;
            if (pos < CAP) {
                const size_t idx = ((size_t)t * NE + e) * CAP + pos;
                disp[idx] = 1.0f;
                comb[idx] = p;
            }
            __syncthreads();
        }
    } else {
        __shared__ float sm[512][16];
        if (tid < 512) {
#pragma unroll
            for (int v = 0; v < 16; v++) sm[tid][v] = g_part[(size_t)tid * 16 + v];
        }
        __syncthreads();
        for (int s = 256; s > 0; s >>= 1) {
            if (tid < s)
#pragma unroll
                for (int v = 0; v < 16; v++) sm[tid][v] += sm[tid + s][v];
            __syncthreads();
        }
        if (tid == 0) {
            float ent = 0.0f;
#pragma unroll
            for (int e = 0; e < NE; e++) {
                const float r = sm[0][e] / (float)N_TOK;
                ent += r * logf(r * 8.0f + 1e-9f);
            }
            float tot = 0.0f;
            float SI[NE];
#pragma unroll
            for (int e = 0; e < NE; e++) { SI[e] = sm[0][NE + e] + 1e-9f; tot += SI[e]; }
            float ie = 0.0f;
#pragma unroll
            for (int e = 0; e < NE; e++) {
                const float ip = SI[e] / tot;
                ie -= ip * logf(ip + 1e-9f);
            }
            out_aux[0] = ent - 0.1f * (ie / logf(8.0f));
        }
    }
}

// ================= launch ==========================================================
extern "C" void kernel_launch(void* const* d_in, const int* in_sizes, int n_in,
                              void* d_out, int out_size) {
    const float* x   = (const float*)d_in[0];
    const float* wi1 = (const float*)d_in[1];
    const float* bi1 = (const float*)d_in[2];
    const float* wi2 = (const float*)d_in[3];
    const float* bi2 = (const float*)d_in[4];
    const float* wr1 = (const float*)d_in[5];
    const float* br1 = (const float*)d_in[6];
    const float* wr2 = (const float*)d_in[7];
    const float* br2 = (const float*)d_in[8];
    const float* wu1 = (const float*)d_in[9];
    const float* bu1 = (const float*)d_in[10];
    const float* wu2 = (const float*)d_in[11];
    const float* bu2 = (const float*)d_in[12];

    float* out   = (float*)d_out;
    float* disp  = out;                                   // [4096, 8, 1536]
    float* comb  = disp + (size_t)N_TOK * NE * CAP;       // [4096, 8, 1536]
    float* probs = comb + (size_t)N_TOK * NE * CAP;       // [4096, 8]
    float* aux   = probs + (size_t)N_TOK * NE;            // [1]
    float* imp   = aux + 1;                               // [4096]

    cudaFuncSetAttribute(gemmA_tc, cudaFuncAttributeMaxDynamicSharedMemorySize, SMEM_A_TC);
    cudaFuncSetAttribute(gemmC_tc, cudaFuncAttributeMaxDynamicSharedMemorySize, SMEM_C_TC);

    prep_kernel<<<NZ1 + 2560 + 512, 256>>>(x, wi1, wr1, wu1, (float4*)disp);
    gemmA_tc<<<148, 256, SMEM_A_TC>>>(bi1, (float4*)disp);
    importance_kernel<<<512, 256>>>(wi2, bi2, imp);
    compact_kernel<<<1, 1024>>>();
    gemmC_tc<<<dim3(4, 34), 256, SMEM_C_TC>>>(br1, bu1);
    routing_kernel<<<512, 256>>>(wr2, br2, wu2, bu2, probs);
    dispatch_aux_kernel<<<2, 1024>>>(disp, comb, aux);
}